// round 8
// baseline (speedup 1.0000x reference)
#include <cuda_runtime.h>

// TSM for fixed shape x=[8,16,96,112,112] fp32, k=4, elements=3.
//   c%3==0: out[t] = (t < 12) ? 0 : x[t]
//   c%3==1: out[t] = (t <  4) ? 0 : x[t-4]
//   c%3==2: out[t] = x[t]
// 256-bit (v8.f32) loads/stores — sm_100+/PTX 8.6 feature. One block per
// plane: 224 threads x 7 v8 = 1568 v8 = 12544 floats. Single 7-deep batch
// doubles bytes-in-flight per lane vs float4 (224 B vs 112 B) with half the
// LDG/STG instruction count, probing the L1tex wavefront-queue limit.

static constexpr int B = 8;
static constexpr int T = 16;
static constexpr int C = 96;
static constexpr int HW = 112 * 112;            // 12544
static constexpr int V8_PER_PLANE = HW / 8;     // 1568
static constexpr int K_SHIFT = 4;
static constexpr int PLANES = B * T * C;        // 12288
static constexpr int THREADS = 224;
static constexpr int VPT = 7;                   // 224*7 = 1568
static constexpr int SHIFT_V8 = K_SHIFT * C * V8_PER_PLANE;  // 602112

struct alignas(32) F8 { float4 a, b; };

__device__ __forceinline__ F8 ldg256_cs(const F8* p) {
    F8 r;
    asm volatile("ld.global.cs.v8.f32 {%0,%1,%2,%3,%4,%5,%6,%7}, [%8];"
        : "=f"(r.a.x), "=f"(r.a.y), "=f"(r.a.z), "=f"(r.a.w),
          "=f"(r.b.x), "=f"(r.b.y), "=f"(r.b.z), "=f"(r.b.w)
        : "l"(p));
    return r;
}

__device__ __forceinline__ void stg256_cs(F8* p, const F8& v) {
    asm volatile("st.global.cs.v8.f32 [%0], {%1,%2,%3,%4,%5,%6,%7,%8};"
        :: "l"(p),
           "f"(v.a.x), "f"(v.a.y), "f"(v.a.z), "f"(v.a.w),
           "f"(v.b.x), "f"(v.b.y), "f"(v.b.z), "f"(v.b.w)
        : "memory");
}

__global__ __launch_bounds__(THREADS)
void tsm_kernel(const F8* __restrict__ x, F8* __restrict__ out) {
    const int plane = blockIdx.x;
    const int c = plane % C;
    const int t = (plane / C) % T;
    const int m = c % 3;

    const long long base = (long long)plane * V8_PER_PLANE + threadIdx.x;
    F8* __restrict__ o = out + base;

    const bool zero = (m == 0 && t < T - K_SHIFT) || (m == 1 && t < K_SHIFT);

    if (zero) {
        F8 z;
        z.a = make_float4(0.f, 0.f, 0.f, 0.f);
        z.b = z.a;
        #pragma unroll
        for (int i = 0; i < VPT; i++)
            stg256_cs(&o[i * THREADS], z);
    } else {
        const F8* __restrict__ src = x + base
            - (m == 1 ? (long long)SHIFT_V8 : 0LL);
        F8 v[VPT];
        #pragma unroll
        for (int i = 0; i < VPT; i++)
            v[i] = ldg256_cs(&src[i * THREADS]);
        #pragma unroll
        for (int i = 0; i < VPT; i++)
            stg256_cs(&o[i * THREADS], v[i]);
    }
}

extern "C" void kernel_launch(void* const* d_in, const int* in_sizes, int n_in,
                              void* d_out, int out_size) {
    const F8* x = (const F8*)d_in[0];
    F8* out = (F8*)d_out;
    tsm_kernel<<<PLANES, THREADS>>>(x, out);
}

// round 9
// speedup vs baseline: 1.0006x; 1.0006x over previous
#include <cuda_runtime.h>

// TSM for fixed shape x=[8,16,96,112,112] fp32, k=4, elements=3.
//   c%3==0: out[t] = (t < 12) ? 0 : x[t]
//   c%3==1: out[t] = (t <  4) ? 0 : x[t-4]
//   c%3==2: out[t] = x[t]
//
// FINAL config — empirical best across 8 measured variants (146.0us kernel,
// 84.0% DRAM, 6.66 TB/s):
//   - Plane (b,t,c) = 12544 floats = 3136 float4; work unit = HALF plane.
//   - 224 threads x 7 float4, single front-batched load group (MLP=7).
//   - Natural register allocation (38 regs -> 7 CTAs/SM). Capping to 32 for
//     9 CTAs/SM measured WORSE (cross-CTA L1tex queue contention).
//   - Plain non-persistent launch: hardware dispatches blocks in address
//     order, keeping concurrent DRAM traffic spatially dense (persistent
//     grid-stride blocks measured 72% DRAM vs 84%).
//   - No .cs hints / no v8 accesses: both measured neutral.
// Workload is pinned at the HBM mixed read/write ceiling (~83-84% of spec);
// occupancy 33%..77% and MLP 4..7 all produce identical bandwidth.

static constexpr int B = 8;
static constexpr int T = 16;
static constexpr int C = 96;
static constexpr int HW = 112 * 112;          // 12544
static constexpr int VEC_PER_PLANE = HW / 4;  // 3136
static constexpr int K_SHIFT = 4;
static constexpr int PLANES = B * T * C;      // 12288
static constexpr int THREADS = 224;
static constexpr int VPT = 7;                 // 224*7 = 1568 = plane/2
static constexpr int HALF_VEC = THREADS * VPT;

__global__ __launch_bounds__(THREADS)
void tsm_kernel(const float4* __restrict__ x, float4* __restrict__ out) {
    const int blk   = blockIdx.x;
    const int plane = blk >> 1;
    const int half  = blk & 1;

    const int c = plane % C;
    const int t = (plane / C) % T;
    const int m = c % 3;

    const long long base = (long long)plane * VEC_PER_PLANE
                         + half * HALF_VEC + threadIdx.x;
    float4* __restrict__ o = out + base;

    const bool zero = (m == 0 && t < T - K_SHIFT) || (m == 1 && t < K_SHIFT);

    if (zero) {
        const float4 z = make_float4(0.f, 0.f, 0.f, 0.f);
        #pragma unroll
        for (int i = 0; i < VPT; i++)
            o[i * THREADS] = z;
    } else {
        const float4* __restrict__ src = x + base
            - (m == 1 ? (long long)K_SHIFT * C * VEC_PER_PLANE : 0LL);
        float4 v[VPT];
        #pragma unroll
        for (int i = 0; i < VPT; i++)
            v[i] = src[i * THREADS];
        #pragma unroll
        for (int i = 0; i < VPT; i++)
            o[i * THREADS] = v[i];
    }
}

extern "C" void kernel_launch(void* const* d_in, const int* in_sizes, int n_in,
                              void* d_out, int out_size) {
    const float4* x = (const float4*)d_in[0];
    float4* out = (float4*)d_out;
    tsm_kernel<<<PLANES * 2, THREADS>>>(x, out);
}